// round 10
// baseline (speedup 1.0000x reference)
#include <cuda_runtime.h>
#include <cuda_fp16.h>
#include <cstdint>

#define BATCH 4
#define CIN   320
#define COUT  320
#define HW    4096
#define CK    2880           // K = c*9 + k
#define CAT2  640
// stage: A 32 rows x 272B = 8704 ; B 160 rows x 80B = 12800 ; total 21504, 3 stages
#define STGB  21504
#define SMEMB 64512
#define SMEMB_IM (131072 + 72*264*2)   // planes + transpose stage

// ---------------- device scratch (A/ct/dn are K-major: [b][K][pix]) ----------------
__device__ __half g_Ac[(size_t)BATCH*CK*HW];
__device__ __half g_Ad[(size_t)BATCH*CK*HW];
__device__ __half g_wt[COUT*CK];
__device__ __half g_wd[COUT*CAT2];
__device__ __half g_wu[COUT*COUT];
__device__ __half g_ct[(size_t)BATCH*CAT2*HW];
__device__ __half g_dn[(size_t)BATCH*COUT*HW];
__device__ float  g_hF[(size_t)BATCH*COUT*HW];
__device__ int    g_ci[9*HW];
__device__ float  g_cw[9*HW];
__device__ int4   g_idf[9*HW];
__device__ float4 g_wdf[9*HW];

// ---------------- helpers ----------------
__device__ __forceinline__ uint32_t smem_u32(const void* p) {
    uint32_t a;
    asm("{ .reg .u64 t; cvta.to.shared.u64 t, %1; cvt.u32.u64 %0, t; }" : "=r"(a) : "l"(p));
    return a;
}
__device__ __forceinline__ void cpa16(uint32_t dst, const void* src) {
    asm volatile("cp.async.cg.shared.global [%0], [%1], 16;" :: "r"(dst), "l"(src));
}
#define LDM4(r, addr) \
    asm volatile("ldmatrix.sync.aligned.m8n8.x4.shared.b16 {%0,%1,%2,%3}, [%4];" \
        : "=r"((r)[0]), "=r"((r)[1]), "=r"((r)[2]), "=r"((r)[3]) : "r"(addr))
#define LDM4T(r, addr) \
    asm volatile("ldmatrix.sync.aligned.m8n8.x4.trans.shared.b16 {%0,%1,%2,%3}, [%4];" \
        : "=r"((r)[0]), "=r"((r)[1]), "=r"((r)[2]), "=r"((r)[3]) : "r"(addr))
#define MMA_F16(c, a, bq) \
    asm volatile("mma.sync.aligned.m16n8k16.row.col.f32.f16.f16.f32 " \
        "{%0,%1,%2,%3}, {%4,%5,%6,%7}, {%8,%9}, {%0,%1,%2,%3};" \
        : "+f"((c)[0]), "+f"((c)[1]), "+f"((c)[2]), "+f"((c)[3]) \
        : "r"((a)[0]), "r"((a)[1]), "r"((a)[2]), "r"((a)[3]), "r"((bq)[0]), "r"((bq)[1]))

__device__ __forceinline__ uint32_t hpack(__half a, __half b) {
    return (uint32_t)__half_as_ushort(a) | ((uint32_t)__half_as_ushort(b) << 16);
}

// ---------------- launch #1: table precompute ----------------
__global__ void precompute(const float* __restrict__ off) {
    int t = blockIdx.x * 256 + threadIdx.x;
    if (t >= 9 * HW) return;
    int k = t >> 12, p = t & 4095;
    int r = p >> 6, c = p & 63;
    int rr = r + k / 3 - 1, qq = c + k % 3 - 1;
    bool vb = (rr >= 0 && rr < 64 && qq >= 0 && qq < 64);
    g_ci[t] = vb ? rr * 64 + qq : 0;
    g_cw[t] = vb ? 1.f : 0.f;
    float dy = off[((k*2+0) << 12) + p];
    float dx = off[((k*2+1) << 12) + p];
    float py = (float)rr + dy, px = (float)qq + dx;
    float y0f = floorf(py), x0f = floorf(px);
    int y0 = (int)y0f, x0 = (int)x0f;
    float wy = py - y0f, wx = px - x0f;
    float wv[4] = { (1.f-wy)*(1.f-wx), (1.f-wy)*wx, wy*(1.f-wx), wy*wx };
    int   idx[4]; float wgt[4];
#pragma unroll
    for (int j = 0; j < 4; j++) {
        int yy = y0 + (j >> 1), xx = x0 + (j & 1);
        bool ok = (yy >= 0 && yy < 64 && xx >= 0 && xx < 64);
        idx[j] = (min(max(yy,0),63) << 6) + min(max(xx,0),63);
        wgt[j] = ok ? wv[j] : 0.f;
    }
    g_idf[t] = make_int4(idx[0], idx[1], idx[2], idx[3]);
    g_wdf[t] = make_float4(wgt[0], wgt[1], wgt[2], wgt[3]);
}

// ---------------- launch #2: weight conversions ----------------
#define NW1 (COUT*CK)
#define NW2 (COUT*CAT2)
#define NW3 (COUT*COUT)
__global__ void prep_w(const float* __restrict__ w, const float* __restrict__ wdn,
                       const float* __restrict__ wup,
                       __half* wt, __half* wd, __half* wu) {
    int i = blockIdx.x * 256 + threadIdx.x;
    if (i < NW1) wt[i] = __float2half_rn(w[i]);
    else if (i < NW1 + NW2) wd[i - NW1] = __float2half_rn(wdn[i - NW1]);
    else if (i < NW1 + NW2 + NW3) wu[i - NW1 - NW2] = __float2half_rn(wup[i - NW1 - NW2]);
}

// ---------------- launch #3: fused im2col -> K-major A, coalesced writes ----------------
#define TVP 264   // stage pitch in halves
__global__ __launch_bounds__(256) void im2col_fused(
    const float* __restrict__ x,
    __half* __restrict__ Ac, __half* __restrict__ Ad)
{
    extern __shared__ char sm[];
    float* pl  = (float*)sm;                 // 8 channel planes = 128KB
    __half* tvs = (__half*)(sm + 131072);    // 72 rows x 264 halves
    int b  = blockIdx.y;
    int c0 = blockIdx.x * 8;
    int tid = threadIdx.x;
    for (int idx = tid; idx < 8 * 4096; idx += 256)
        pl[idx] = x[(((size_t)b * CIN + c0) << 12) + idx];
    __syncthreads();

    for (int p0 = 0; p0 < 4096; p0 += 256) {
        int p = p0 + tid;
        // ---- conv taps ----
#pragma unroll
        for (int k = 0; k < 9; k++) {
            int   ci = g_ci[(k << 12) + p];
            float cw = g_cw[(k << 12) + p];
#pragma unroll
            for (int c = 0; c < 8; c++)
                tvs[(c * 9 + k) * TVP + tid] = __float2half_rn(cw * pl[(c << 12) + ci]);
        }
        __syncthreads();
#pragma unroll
        for (int it = 0; it < 9; it++) {
            int idx = it * 256 + tid;
            int r = idx >> 5, jj = idx & 31;
            uint4 v = *(const uint4*)(tvs + r * TVP + jj * 8);
            *(uint4*)(Ac + ((size_t)b * CK + c0 * 9 + r) * HW + p0 + jj * 8) = v;
        }
        __syncthreads();
        // ---- deformable taps ----
#pragma unroll
        for (int k = 0; k < 9; k++) {
            int4   di = g_idf[(k << 12) + p];
            float4 dw = g_wdf[(k << 12) + p];
#pragma unroll
            for (int c = 0; c < 8; c++) {
                const float* q = pl + (c << 12);
                float v = dw.x*q[di.x] + dw.y*q[di.y] + dw.z*q[di.z] + dw.w*q[di.w];
                tvs[(c * 9 + k) * TVP + tid] = __float2half_rn(v);
            }
        }
        __syncthreads();
#pragma unroll
        for (int it = 0; it < 9; it++) {
            int idx = it * 256 + tid;
            int r = idx >> 5, jj = idx & 31;
            uint4 v = *(const uint4*)(tvs + r * TVP + jj * 8);
            *(uint4*)(Ad + ((size_t)b * CK + c0 * 9 + r) * HW + p0 + jj * 8) = v;
        }
        __syncthreads();
    }
}

// ---------------- HMMA GEMM: A K-major [b][K][pix], B [ch][K]; D[128 pix][160 ch] ----------------
// MODE 0 (big): grid.y = asel*2+nsl; asel=0 -> A=def -> ct[0:320]; asel=1 -> A=conv -> ct[320:640]+hF.
// MODE 1 (down): A=ct (K=640) -> dn.   MODE 2 (up): A=dn (K=320) -> out = hF + scale*acc.
template<int MODE>
__global__ void __launch_bounds__(256, 2) gemm_mma(
    const __half* __restrict__ A0, const __half* __restrict__ A1,
    const __half* __restrict__ B,
    int K, const float* __restrict__ bias, float* __restrict__ hF,
    __half* __restrict__ O,
    float* __restrict__ out, const float* __restrict__ scalep)
{
    extern __shared__ char smem[];
    uint32_t sb = smem_u32(smem);
    float* fst = (float*)smem;                  // epilogue stage [80][132]
    int tid = threadIdx.x;
    int b = blockIdx.z;
    int pix0 = blockIdx.x * 128;
    int ys = blockIdx.y;
    int asel = (MODE == 0) ? (ys >> 1) : 0;
    int nsl  = (MODE == 0) ? (ys & 1) : ys;
    int NCH = K >> 5;

    const __half* Ab = ((MODE == 0 && asel) ? A1 : A0) + (size_t)b * K * HW + pix0;
    const __half* Bs = B + (size_t)(nsl * 160) * K;

    int w = tid >> 5, lane = tid & 31;
    int m0 = (w & 3) * 32;
    int ngr = w >> 2;                 // 0/1: 80-ch group within the 160 slice
    // A (trans ldmatrix): k-offset from bit4, m-offset from bit3
    int at_k = (lane & 7) + ((lane >> 4) & 1) * 8;
    int at_m = ((lane >> 3) & 1) * 8;
    // B (normal ldmatrix on [ch][k] tiles)
    int b_r = (lane & 7) + ((lane >> 4) & 1) * 8;
    int b_c = ((lane >> 3) & 1) * 16;

    float acc[2][10][4];
#pragma unroll
    for (int i = 0; i < 2; i++)
#pragma unroll
        for (int j = 0; j < 10; j++)
#pragma unroll
            for (int q = 0; q < 4; q++) acc[i][j][q] = 0.f;

    auto load_stage = [&](int ci) {
        uint32_t st = sb + (uint32_t)(ci % 3) * STGB;
        int k0 = ci << 5;
#pragma unroll
        for (int it = 0; it < 2; it++) {        // A: 32 k-rows x 256B
            int idx = tid + it * 256;
            int r = idx >> 4, j = idx & 15;
            cpa16(st + r * 272 + j * 16, Ab + (size_t)(k0 + r) * HW + j * 8);
        }
#pragma unroll
        for (int it = 0; it < 3; it++) {        // B: 160 ch-rows x 64B
            int idx = tid + it * 256;
            if (idx < 640) {
                int r = idx >> 2, j = idx & 3;
                cpa16(st + 8704 + r * 80 + j * 16, Bs + (size_t)r * K + k0 + j * 8);
            }
        }
        asm volatile("cp.async.commit_group;" ::: "memory");
    };

    load_stage(0);
    load_stage(1);
    asm volatile("cp.async.wait_group 1;" ::: "memory");
    __syncthreads();

    for (int i = 0; i < NCH; i++) {
        if (i + 2 < NCH) load_stage(i + 2);
        else asm volatile("cp.async.commit_group;" ::: "memory");
        uint32_t st = sb + (uint32_t)(i % 3) * STGB;
#pragma unroll
        for (int kk = 0; kk < 2; kk++) {
            uint32_t ah[2][4];
#pragma unroll
            for (int mf = 0; mf < 2; mf++) {
                uint32_t ad = st + (uint32_t)(kk * 16 + at_k) * 272
                                 + (uint32_t)(m0 + mf * 16 + at_m) * 2;
                LDM4T(ah[mf], ad);
            }
#pragma unroll
            for (int np = 0; np < 5; np++) {
                uint32_t bh[4];
                uint32_t bd = st + 8704 + (uint32_t)(ngr * 80 + np * 16 + b_r) * 80 + kk * 32 + b_c;
                LDM4(bh, bd);
#pragma unroll
                for (int mf = 0; mf < 2; mf++)
#pragma unroll
                    for (int h = 0; h < 2; h++)
                        MMA_F16(acc[mf][np * 2 + h], ah[mf], bh + 2 * h);
            }
        }
        asm volatile("cp.async.wait_group 1;" ::: "memory");
        __syncthreads();
    }

    // ---- epilogue: 2 groups of 80 channels via smem [80][132]; all outputs ch-major ----
    float sc = (MODE == 2) ? *scalep : 0.f;
    for (int g = 0; g < 2; g++) {
        if (ngr == g) {
#pragma unroll
            for (int mf = 0; mf < 2; mf++)
#pragma unroll
                for (int nf = 0; nf < 10; nf++) {
                    int pr = m0 + mf * 16 + (lane >> 2);
                    int nc = nf * 8 + 2 * (lane & 3);
                    fst[nc * 132 + pr]           = acc[mf][nf][0];
                    fst[(nc + 1) * 132 + pr]     = acc[mf][nf][1];
                    fst[nc * 132 + pr + 8]       = acc[mf][nf][2];
                    fst[(nc + 1) * 132 + pr + 8] = acc[mf][nf][3];
                }
        }
        __syncthreads();
        int chbase = nsl * 160 + g * 80;               // output channel base (0..319)

        if (MODE == 2) {
            for (int idx = tid; idx < 80 * 128; idx += 256) {
                int n = idx >> 7, p = idx & 127;
                size_t o = (((size_t)b * COUT + chbase + n) << 12) + pix0 + p;
                out[o] = hF[o] + sc * fst[n * 132 + p];
            }
        } else {
            if (MODE == 0 && asel == 1) {
                for (int idx = tid; idx < 80 * 128; idx += 256) {
                    int n = idx >> 7, p = idx & 127;
                    float v = fst[n * 132 + p] + __ldg(bias + chbase + n);
                    hF[(((size_t)b * COUT + chbase + n) << 12) + pix0 + p] = v;
                }
            }
            int obase = (MODE == 0) ? (asel * 320 + chbase) : chbase;
            int odim  = (MODE == 0) ? CAT2 : COUT;
            for (int idx = tid; idx < 80 * 64; idx += 256) {
                int n = idx >> 6, p2 = idx & 63;
                float v0 = fst[n * 132 + p2 * 2];
                float v1 = fst[n * 132 + p2 * 2 + 1];
                if (MODE == 0) {
                    float bv = __ldg(bias + chbase + n);
                    v0 += bv; v1 += bv;
                }
                *(uint32_t*)(O + (((size_t)b * odim + obase + n) << 12) + pix0 + p2 * 2)
                    = hpack(__float2half_rn(v0), __float2half_rn(v1));
            }
        }
        __syncthreads();
    }
}

// ---------------- launch ----------------
extern "C" void kernel_launch(void* const* d_in, const int* in_sizes, int n_in,
                              void* d_out, int out_size) {
    const float* x      = (const float*)d_in[0];
    const float* weight = (const float*)d_in[1];
    const float* bias   = (const float*)d_in[2];
    const float* w_down = (const float*)d_in[3];
    const float* w_up   = (const float*)d_in[4];
    const float* scale  = (const float*)d_in[5];
    const float* offset = (const float*)d_in[6];
    float* out = (float*)d_out;

    __half *Ac, *Ad, *wt, *wd, *wu, *ct, *dn;
    float *hF;
    cudaGetSymbolAddress((void**)&Ac, g_Ac); cudaGetSymbolAddress((void**)&Ad, g_Ad);
    cudaGetSymbolAddress((void**)&wt, g_wt); cudaGetSymbolAddress((void**)&wd, g_wd);
    cudaGetSymbolAddress((void**)&wu, g_wu);
    cudaGetSymbolAddress((void**)&ct, g_ct); cudaGetSymbolAddress((void**)&dn, g_dn);
    cudaGetSymbolAddress((void**)&hF, g_hF);

    cudaFuncSetAttribute(im2col_fused, cudaFuncAttributeMaxDynamicSharedMemorySize, SMEMB_IM);
    cudaFuncSetAttribute(gemm_mma<0>, cudaFuncAttributeMaxDynamicSharedMemorySize, SMEMB);
    cudaFuncSetAttribute(gemm_mma<1>, cudaFuncAttributeMaxDynamicSharedMemorySize, SMEMB);
    cudaFuncSetAttribute(gemm_mma<2>, cudaFuncAttributeMaxDynamicSharedMemorySize, SMEMB);

    precompute<<<(9 * HW + 255) / 256, 256>>>(offset);
    prep_w<<<(NW1 + NW2 + NW3 + 255) / 256, 256>>>(weight, w_down, w_up, wt, wd, wu);
    im2col_fused<<<dim3(40, BATCH), 256, SMEMB_IM>>>(x, Ac, Ad);

    // launch #4 (profiled): big dual GEMM, grid.y = asel*2 + nsl
    gemm_mma<0><<<dim3(HW / 128, 4, BATCH), 256, SMEMB>>>(
        Ad, Ac, wt, CK, bias, hF, ct, nullptr, nullptr);
    // down = w_down @ cat -> dn
    gemm_mma<1><<<dim3(HW / 128, 2, BATCH), 256, SMEMB>>>(
        ct, nullptr, wd, CAT2, nullptr, nullptr, dn, nullptr, nullptr);
    // out = hF + scale * (w_up @ dn)
    gemm_mma<2><<<dim3(HW / 128, 2, BATCH), 256, SMEMB>>>(
        dn, nullptr, wu, COUT, nullptr, hF, nullptr, out, scale);
}

// round 11
// speedup vs baseline: 1.3607x; 1.3607x over previous
#include <cuda_runtime.h>
#include <cuda_fp16.h>
#include <cstdint>

#define BATCH 4
#define CIN   320
#define COUT  320
#define HW    4096
#define CK    2880           // K = c*9 + k
#define CAT2  640
// GEMM stage: A 32 rows x 272B = 8704 ; B 160 rows x 80B = 12800 ; total 21504, 3 stages
#define STGB  21504
#define SMEMB 64512

// ---------------- device scratch (A/ct/dn K-major: [b][K][pix]) ----------------
__device__ __half g_xh[(size_t)BATCH*CIN*HW];
__device__ __half g_Ac[(size_t)BATCH*CK*HW];
__device__ __half g_Ad[(size_t)BATCH*CK*HW];
__device__ __half g_wt[COUT*CK];
__device__ __half g_wd[COUT*CAT2];
__device__ __half g_wu[COUT*COUT];
__device__ __half g_ct[(size_t)BATCH*CAT2*HW];
__device__ __half g_dn[(size_t)BATCH*COUT*HW];
__device__ float  g_hF[(size_t)BATCH*COUT*HW];
__device__ int    g_ci[9*HW];
__device__ float  g_cw[9*HW];
__device__ int4   g_idf[9*HW];
__device__ float4 g_wdf[9*HW];

// ---------------- helpers ----------------
__device__ __forceinline__ uint32_t smem_u32(const void* p) {
    uint32_t a;
    asm("{ .reg .u64 t; cvta.to.shared.u64 t, %1; cvt.u32.u64 %0, t; }" : "=r"(a) : "l"(p));
    return a;
}
__device__ __forceinline__ void cpa16(uint32_t dst, const void* src) {
    asm volatile("cp.async.cg.shared.global [%0], [%1], 16;" :: "r"(dst), "l"(src));
}
#define LDM4(r, addr) \
    asm volatile("ldmatrix.sync.aligned.m8n8.x4.shared.b16 {%0,%1,%2,%3}, [%4];" \
        : "=r"((r)[0]), "=r"((r)[1]), "=r"((r)[2]), "=r"((r)[3]) : "r"(addr))
#define LDM4T(r, addr) \
    asm volatile("ldmatrix.sync.aligned.m8n8.x4.trans.shared.b16 {%0,%1,%2,%3}, [%4];" \
        : "=r"((r)[0]), "=r"((r)[1]), "=r"((r)[2]), "=r"((r)[3]) : "r"(addr))
#define MMA_F16(c, a, bq) \
    asm volatile("mma.sync.aligned.m16n8k16.row.col.f32.f16.f16.f32 " \
        "{%0,%1,%2,%3}, {%4,%5,%6,%7}, {%8,%9}, {%0,%1,%2,%3};" \
        : "+f"((c)[0]), "+f"((c)[1]), "+f"((c)[2]), "+f"((c)[3]) \
        : "r"((a)[0]), "r"((a)[1]), "r"((a)[2]), "r"((a)[3]), "r"((bq)[0]), "r"((bq)[1]))

__device__ __forceinline__ uint32_t hpack(__half a, __half b) {
    return (uint32_t)__half_as_ushort(a) | ((uint32_t)__half_as_ushort(b) << 16);
}

// ---------------- launch #1: table precompute ----------------
__global__ void precompute(const float* __restrict__ off) {
    int t = blockIdx.x * 256 + threadIdx.x;
    if (t >= 9 * HW) return;
    int k = t >> 12, p = t & 4095;
    int r = p >> 6, c = p & 63;
    int rr = r + k / 3 - 1, qq = c + k % 3 - 1;
    bool vb = (rr >= 0 && rr < 64 && qq >= 0 && qq < 64);
    g_ci[t] = vb ? rr * 64 + qq : 0;
    g_cw[t] = vb ? 1.f : 0.f;
    float dy = off[((k*2+0) << 12) + p];
    float dx = off[((k*2+1) << 12) + p];
    float py = (float)rr + dy, px = (float)qq + dx;
    float y0f = floorf(py), x0f = floorf(px);
    int y0 = (int)y0f, x0 = (int)x0f;
    float wy = py - y0f, wx = px - x0f;
    float wv[4] = { (1.f-wy)*(1.f-wx), (1.f-wy)*wx, wy*(1.f-wx), wy*wx };
    int   idx[4]; float wgt[4];
#pragma unroll
    for (int j = 0; j < 4; j++) {
        int yy = y0 + (j >> 1), xx = x0 + (j & 1);
        bool ok = (yy >= 0 && yy < 64 && xx >= 0 && xx < 64);
        idx[j] = (min(max(yy,0),63) << 6) + min(max(xx,0),63);
        wgt[j] = ok ? wv[j] : 0.f;
    }
    g_idf[t] = make_int4(idx[0], idx[1], idx[2], idx[3]);
    g_wdf[t] = make_float4(wgt[0], wgt[1], wgt[2], wgt[3]);
}

// ---------------- launch #2: weight conversions ----------------
#define NW1 (COUT*CK)
#define NW2 (COUT*CAT2)
#define NW3 (COUT*COUT)
__global__ void prep_w(const float* __restrict__ w, const float* __restrict__ wdn,
                       const float* __restrict__ wup,
                       __half* wt, __half* wd, __half* wu) {
    int i = blockIdx.x * 256 + threadIdx.x;
    if (i < NW1) wt[i] = __float2half_rn(w[i]);
    else if (i < NW1 + NW2) wd[i - NW1] = __float2half_rn(wdn[i - NW1]);
    else if (i < NW1 + NW2 + NW3) wu[i - NW1 - NW2] = __float2half_rn(wup[i - NW1 - NW2]);
}

// ---------------- launch #3: x -> fp16 ----------------
__global__ void to_xh(const float* __restrict__ x, __half* __restrict__ xh) {
    size_t i = ((size_t)blockIdx.x * 256 + threadIdx.x) * 8;
    float4 a = *(const float4*)(x + i);
    float4 b = *(const float4*)(x + i + 4);
    uint4 o;
    o.x = hpack(__float2half_rn(a.x), __float2half_rn(a.y));
    o.y = hpack(__float2half_rn(a.z), __float2half_rn(a.w));
    o.z = hpack(__float2half_rn(b.x), __float2half_rn(b.y));
    o.w = hpack(__float2half_rn(b.z), __float2half_rn(b.w));
    *(uint4*)(xh + i) = o;
}

// ---------------- launch #4 (profiled): per-tap im2col -> K-major A ----------------
// grid (40 c-blocks, 9 taps, 4 batch); 8 fp16 planes in smem; writes 512B/warp runs.
__global__ __launch_bounds__(256, 2) void im2col_k(
    const __half* __restrict__ xh,
    __half* __restrict__ Ac, __half* __restrict__ Ad)
{
    __shared__ __half pl[8 * 4096];     // 64KB
    int b = blockIdx.z, k = blockIdx.y, c0 = blockIdx.x * 8;
    int tid = threadIdx.x;
    const uint4* src = (const uint4*)(xh + (((size_t)b * CIN + c0) << 12));
    for (int i = tid; i < 4096; i += 256) ((uint4*)pl)[i] = src[i];
    __syncthreads();

    for (int it = 0; it < 2; it++) {
        int p0 = it * 2048 + tid * 8;
        // ---- conv tap (single shifted copy, weight 0/1) ----
        {
            int ci[8]; float cw[8];
#pragma unroll
            for (int j = 0; j < 8; j++) {
                ci[j] = g_ci[(k << 12) + p0 + j];
                cw[j] = g_cw[(k << 12) + p0 + j];
            }
#pragma unroll
            for (int c = 0; c < 8; c++) {
                __half v[8];
#pragma unroll
                for (int j = 0; j < 8; j++)
                    v[j] = (cw[j] != 0.f) ? pl[(c << 12) + ci[j]] : __ushort_as_half((unsigned short)0);
                *(uint4*)(Ac + (((size_t)b * CK + (c0 + c) * 9 + k) << 12) + p0) = *(uint4*)v;
            }
        }
        // ---- deformable tap (bilinear over fp16 planes) ----
        {
            int4 di[8]; float4 dw[8];
#pragma unroll
            for (int j = 0; j < 8; j++) {
                di[j] = g_idf[(k << 12) + p0 + j];
                dw[j] = g_wdf[(k << 12) + p0 + j];
            }
#pragma unroll
            for (int c = 0; c < 8; c++) {
                const __half* q = pl + (c << 12);
                __half v[8];
#pragma unroll
                for (int j = 0; j < 8; j++) {
                    float val = dw[j].x * __half2float(q[di[j].x])
                              + dw[j].y * __half2float(q[di[j].y])
                              + dw[j].z * __half2float(q[di[j].z])
                              + dw[j].w * __half2float(q[di[j].w]);
                    v[j] = __float2half_rn(val);
                }
                *(uint4*)(Ad + (((size_t)b * CK + (c0 + c) * 9 + k) << 12) + p0) = *(uint4*)v;
            }
        }
    }
}

// ---------------- HMMA GEMM (R10 form): A K-major [b][K][pix], B [ch][K] ----------------
// MODE 0 (big): grid.y = asel*2+nsl; asel=0 -> A=def -> ct[0:320]; asel=1 -> A=conv -> ct[320:640]+hF.
// MODE 1 (down): A=ct (K=640) -> dn.   MODE 2 (up): A=dn (K=320) -> out = hF + scale*acc.
template<int MODE>
__global__ void __launch_bounds__(256, 2) gemm_mma(
    const __half* __restrict__ A0, const __half* __restrict__ A1,
    const __half* __restrict__ B,
    int K, const float* __restrict__ bias, float* __restrict__ hF,
    __half* __restrict__ O,
    float* __restrict__ out, const float* __restrict__ scalep)
{
    extern __shared__ char smem[];
    uint32_t sb = smem_u32(smem);
    float* fst = (float*)smem;                  // epilogue stage [80][132]
    int tid = threadIdx.x;
    int b = blockIdx.z;
    int pix0 = blockIdx.x * 128;
    int ys = blockIdx.y;
    int asel = (MODE == 0) ? (ys >> 1) : 0;
    int nsl  = (MODE == 0) ? (ys & 1) : ys;
    int NCH = K >> 5;

    const __half* Ab = ((MODE == 0 && asel) ? A1 : A0) + (size_t)b * K * HW + pix0;
    const __half* Bs = B + (size_t)(nsl * 160) * K;

    int w = tid >> 5, lane = tid & 31;
    int m0 = (w & 3) * 32;
    int ngr = w >> 2;
    int at_k = (lane & 7) + ((lane >> 4) & 1) * 8;
    int at_m = ((lane >> 3) & 1) * 8;
    int b_r = (lane & 7) + ((lane >> 4) & 1) * 8;
    int b_c = ((lane >> 3) & 1) * 16;

    float acc[2][10][4];
#pragma unroll
    for (int i = 0; i < 2; i++)
#pragma unroll
        for (int j = 0; j < 10; j++)
#pragma unroll
            for (int q = 0; q < 4; q++) acc[i][j][q] = 0.f;

    auto load_stage = [&](int ci) {
        uint32_t st = sb + (uint32_t)(ci % 3) * STGB;
        int k0 = ci << 5;
#pragma unroll
        for (int it = 0; it < 2; it++) {        // A: 32 k-rows x 256B
            int idx = tid + it * 256;
            int r = idx >> 4, j = idx & 15;
            cpa16(st + r * 272 + j * 16, Ab + (size_t)(k0 + r) * HW + j * 8);
        }
#pragma unroll
        for (int it = 0; it < 3; it++) {        // B: 160 ch-rows x 64B
            int idx = tid + it * 256;
            if (idx < 640) {
                int r = idx >> 2, j = idx & 3;
                cpa16(st + 8704 + r * 80 + j * 16, Bs + (size_t)r * K + k0 + j * 8);
            }
        }
        asm volatile("cp.async.commit_group;" ::: "memory");
    };

    load_stage(0);
    load_stage(1);
    asm volatile("cp.async.wait_group 1;" ::: "memory");
    __syncthreads();

    for (int i = 0; i < NCH; i++) {
        if (i + 2 < NCH) load_stage(i + 2);
        else asm volatile("cp.async.commit_group;" ::: "memory");
        uint32_t st = sb + (uint32_t)(i % 3) * STGB;
#pragma unroll
        for (int kk = 0; kk < 2; kk++) {
            uint32_t ah[2][4];
#pragma unroll
            for (int mf = 0; mf < 2; mf++) {
                uint32_t ad = st + (uint32_t)(kk * 16 + at_k) * 272
                                 + (uint32_t)(m0 + mf * 16 + at_m) * 2;
                LDM4T(ah[mf], ad);
            }
#pragma unroll
            for (int np = 0; np < 5; np++) {
                uint32_t bh[4];
                uint32_t bd = st + 8704 + (uint32_t)(ngr * 80 + np * 16 + b_r) * 80 + kk * 32 + b_c;
                LDM4(bh, bd);
#pragma unroll
                for (int mf = 0; mf < 2; mf++)
#pragma unroll
                    for (int h = 0; h < 2; h++)
                        MMA_F16(acc[mf][np * 2 + h], ah[mf], bh + 2 * h);
            }
        }
        asm volatile("cp.async.wait_group 1;" ::: "memory");
        __syncthreads();
    }

    float sc = (MODE == 2) ? *scalep : 0.f;
    for (int g = 0; g < 2; g++) {
        if (ngr == g) {
#pragma unroll
            for (int mf = 0; mf < 2; mf++)
#pragma unroll
                for (int nf = 0; nf < 10; nf++) {
                    int pr = m0 + mf * 16 + (lane >> 2);
                    int nc = nf * 8 + 2 * (lane & 3);
                    fst[nc * 132 + pr]           = acc[mf][nf][0];
                    fst[(nc + 1) * 132 + pr]     = acc[mf][nf][1];
                    fst[nc * 132 + pr + 8]       = acc[mf][nf][2];
                    fst[(nc + 1) * 132 + pr + 8] = acc[mf][nf][3];
                }
        }
        __syncthreads();
        int chbase = nsl * 160 + g * 80;

        if (MODE == 2) {
            for (int idx = tid; idx < 80 * 128; idx += 256) {
                int n = idx >> 7, p = idx & 127;
                size_t o = (((size_t)b * COUT + chbase + n) << 12) + pix0 + p;
                out[o] = hF[o] + sc * fst[n * 132 + p];
            }
        } else {
            if (MODE == 0 && asel == 1) {
                for (int idx = tid; idx < 80 * 128; idx += 256) {
                    int n = idx >> 7, p = idx & 127;
                    float v = fst[n * 132 + p] + __ldg(bias + chbase + n);
                    hF[(((size_t)b * COUT + chbase + n) << 12) + pix0 + p] = v;
                }
            }
            int obase = (MODE == 0) ? (asel * 320 + chbase) : chbase;
            int odim  = (MODE == 0) ? CAT2 : COUT;
            for (int idx = tid; idx < 80 * 64; idx += 256) {
                int n = idx >> 6, p2 = idx & 63;
                float v0 = fst[n * 132 + p2 * 2];
                float v1 = fst[n * 132 + p2 * 2 + 1];
                if (MODE == 0) {
                    float bv = __ldg(bias + chbase + n);
                    v0 += bv; v1 += bv;
                }
                *(uint32_t*)(O + (((size_t)b * odim + obase + n) << 12) + pix0 + p2 * 2)
                    = hpack(__float2half_rn(v0), __float2half_rn(v1));
            }
        }
        __syncthreads();
    }
}

// ---------------- launch ----------------
extern "C" void kernel_launch(void* const* d_in, const int* in_sizes, int n_in,
                              void* d_out, int out_size) {
    const float* x      = (const float*)d_in[0];
    const float* weight = (const float*)d_in[1];
    const float* bias   = (const float*)d_in[2];
    const float* w_down = (const float*)d_in[3];
    const float* w_up   = (const float*)d_in[4];
    const float* scale  = (const float*)d_in[5];
    const float* offset = (const float*)d_in[6];
    float* out = (float*)d_out;

    __half *xh, *Ac, *Ad, *wt, *wd, *wu, *ct, *dn;
    float *hF;
    cudaGetSymbolAddress((void**)&xh, g_xh);
    cudaGetSymbolAddress((void**)&Ac, g_Ac); cudaGetSymbolAddress((void**)&Ad, g_Ad);
    cudaGetSymbolAddress((void**)&wt, g_wt); cudaGetSymbolAddress((void**)&wd, g_wd);
    cudaGetSymbolAddress((void**)&wu, g_wu);
    cudaGetSymbolAddress((void**)&ct, g_ct); cudaGetSymbolAddress((void**)&dn, g_dn);
    cudaGetSymbolAddress((void**)&hF, g_hF);

    cudaFuncSetAttribute(gemm_mma<0>, cudaFuncAttributeMaxDynamicSharedMemorySize, SMEMB);
    cudaFuncSetAttribute(gemm_mma<1>, cudaFuncAttributeMaxDynamicSharedMemorySize, SMEMB);
    cudaFuncSetAttribute(gemm_mma<2>, cudaFuncAttributeMaxDynamicSharedMemorySize, SMEMB);

    // #1, #2
    precompute<<<(9 * HW + 255) / 256, 256>>>(offset);
    prep_w<<<(NW1 + NW2 + NW3 + 255) / 256, 256>>>(weight, w_down, w_up, wt, wd, wu);
    // #3: x -> fp16
    to_xh<<<(BATCH * CIN * HW) / 2048, 256>>>(x, xh);
    // #4 (profiled): per-tap im2col
    im2col_k<<<dim3(40, 9, BATCH), 256>>>(xh, Ac, Ad);
    // #5: big dual GEMM
    gemm_mma<0><<<dim3(HW / 128, 4, BATCH), 256, SMEMB>>>(
        Ad, Ac, wt, CK, bias, hF, ct, nullptr, nullptr);
    // #6: down
    gemm_mma<1><<<dim3(HW / 128, 2, BATCH), 256, SMEMB>>>(
        ct, nullptr, wd, CAT2, nullptr, nullptr, dn, nullptr, nullptr);
    // #7: up + residual
    gemm_mma<2><<<dim3(HW / 128, 2, BATCH), 256, SMEMB>>>(
        dn, nullptr, wu, COUT, nullptr, hF, nullptr, out, scale);
}

// round 12
// speedup vs baseline: 1.7429x; 1.2809x over previous
#include <cuda_runtime.h>
#include <cuda_fp16.h>
#include <cstdint>

#define BATCH 4
#define CIN   320
#define COUT  320
#define HW    4096
#define CK    2880           // K = c*9 + k
#define CAT2  640
// GEMM stage: A 32 rows x 272B = 8704 ; B 160 rows x 80B = 12800 ; total 21504, 3 stages
#define STGB  21504
#define SMEMB 64512

// ---------------- device scratch (A/ct/dn K-major: [b][K][pix]) ----------------
__device__ __half g_xh[(size_t)BATCH*CIN*HW];
__device__ __half g_Ac[(size_t)BATCH*CK*HW];
__device__ __half g_Ad[(size_t)BATCH*CK*HW];
__device__ __half g_wt[COUT*CK];
__device__ __half g_wd[COUT*CAT2];
__device__ __half g_wu[COUT*COUT];
__device__ __half g_ct[(size_t)BATCH*CAT2*HW];
__device__ __half g_dn[(size_t)BATCH*COUT*HW];
__device__ float  g_hF[(size_t)BATCH*COUT*HW];
__device__ int    g_ci[9*HW];
__device__ float  g_cw[9*HW];
__device__ int4   g_idf[9*HW];
__device__ float4 g_wdf[9*HW];

// ---------------- helpers ----------------
__device__ __forceinline__ uint32_t smem_u32(const void* p) {
    uint32_t a;
    asm("{ .reg .u64 t; cvta.to.shared.u64 t, %1; cvt.u32.u64 %0, t; }" : "=r"(a) : "l"(p));
    return a;
}
__device__ __forceinline__ void cpa16(uint32_t dst, const void* src) {
    asm volatile("cp.async.cg.shared.global [%0], [%1], 16;" :: "r"(dst), "l"(src));
}
#define LDM4(r, addr) \
    asm volatile("ldmatrix.sync.aligned.m8n8.x4.shared.b16 {%0,%1,%2,%3}, [%4];" \
        : "=r"((r)[0]), "=r"((r)[1]), "=r"((r)[2]), "=r"((r)[3]) : "r"(addr))
#define LDM4T(r, addr) \
    asm volatile("ldmatrix.sync.aligned.m8n8.x4.trans.shared.b16 {%0,%1,%2,%3}, [%4];" \
        : "=r"((r)[0]), "=r"((r)[1]), "=r"((r)[2]), "=r"((r)[3]) : "r"(addr))
#define MMA_F16(c, a, bq) \
    asm volatile("mma.sync.aligned.m16n8k16.row.col.f32.f16.f16.f32 " \
        "{%0,%1,%2,%3}, {%4,%5,%6,%7}, {%8,%9}, {%0,%1,%2,%3};" \
        : "+f"((c)[0]), "+f"((c)[1]), "+f"((c)[2]), "+f"((c)[3]) \
        : "r"((a)[0]), "r"((a)[1]), "r"((a)[2]), "r"((a)[3]), "r"((bq)[0]), "r"((bq)[1]))

__device__ __forceinline__ uint32_t hpack(__half a, __half b) {
    return (uint32_t)__half_as_ushort(a) | ((uint32_t)__half_as_ushort(b) << 16);
}

// ---------------- launch #1: table precompute ----------------
__global__ void precompute(const float* __restrict__ off) {
    int t = blockIdx.x * 256 + threadIdx.x;
    if (t >= 9 * HW) return;
    int k = t >> 12, p = t & 4095;
    int r = p >> 6, c = p & 63;
    int rr = r + k / 3 - 1, qq = c + k % 3 - 1;
    bool vb = (rr >= 0 && rr < 64 && qq >= 0 && qq < 64);
    g_ci[t] = vb ? rr * 64 + qq : 0;
    g_cw[t] = vb ? 1.f : 0.f;
    float dy = off[((k*2+0) << 12) + p];
    float dx = off[((k*2+1) << 12) + p];
    float py = (float)rr + dy, px = (float)qq + dx;
    float y0f = floorf(py), x0f = floorf(px);
    int y0 = (int)y0f, x0 = (int)x0f;
    float wy = py - y0f, wx = px - x0f;
    float wv[4] = { (1.f-wy)*(1.f-wx), (1.f-wy)*wx, wy*(1.f-wx), wy*wx };
    int   idx[4]; float wgt[4];
#pragma unroll
    for (int j = 0; j < 4; j++) {
        int yy = y0 + (j >> 1), xx = x0 + (j & 1);
        bool ok = (yy >= 0 && yy < 64 && xx >= 0 && xx < 64);
        idx[j] = (min(max(yy,0),63) << 6) + min(max(xx,0),63);
        wgt[j] = ok ? wv[j] : 0.f;
    }
    g_idf[t] = make_int4(idx[0], idx[1], idx[2], idx[3]);
    g_wdf[t] = make_float4(wgt[0], wgt[1], wgt[2], wgt[3]);
}

// ---------------- launch #2: weight conversions ----------------
#define NW1 (COUT*CK)
#define NW2 (COUT*CAT2)
#define NW3 (COUT*COUT)
__global__ void prep_w(const float* __restrict__ w, const float* __restrict__ wdn,
                       const float* __restrict__ wup,
                       __half* wt, __half* wd, __half* wu) {
    int i = blockIdx.x * 256 + threadIdx.x;
    if (i < NW1) wt[i] = __float2half_rn(w[i]);
    else if (i < NW1 + NW2) wd[i - NW1] = __float2half_rn(wdn[i - NW1]);
    else if (i < NW1 + NW2 + NW3) wu[i - NW1 - NW2] = __float2half_rn(wup[i - NW1 - NW2]);
}

// ---------------- launch #3: x -> fp16 ----------------
__global__ void to_xh(const float* __restrict__ x, __half* __restrict__ xh) {
    size_t i = ((size_t)blockIdx.x * 256 + threadIdx.x) * 8;
    float4 a = *(const float4*)(x + i);
    float4 b = *(const float4*)(x + i + 4);
    uint4 o;
    o.x = hpack(__float2half_rn(a.x), __float2half_rn(a.y));
    o.y = hpack(__float2half_rn(a.z), __float2half_rn(a.w));
    o.z = hpack(__float2half_rn(b.x), __float2half_rn(b.y));
    o.w = hpack(__float2half_rn(b.z), __float2half_rn(b.w));
    *(uint4*)(xh + i) = o;
}

// ---------------- launch #4 (profiled): per-tap im2col, conflict-free lanes ----------------
// grid (40 c-blocks, 9 taps, 4 batch). Lane owns pixel pair pb + 2*lane + 64*jj:
// adjacent lanes touch adjacent smem words (no bank conflicts); each (c,pair) is a
// coalesced 4B store (warp = 128B line).
__global__ __launch_bounds__(256, 2) void im2col_k(
    const __half* __restrict__ xh,
    __half* __restrict__ Ac, __half* __restrict__ Ad)
{
    __shared__ __half pl[8 * 4096];     // 64KB
    int b = blockIdx.z, k = blockIdx.y, c0 = blockIdx.x * 8;
    int tid = threadIdx.x;
    int w = tid >> 5, lane = tid & 31;
    const uint4* src = (const uint4*)(xh + (((size_t)b * CIN + c0) << 12));
    for (int i = tid; i < 4096; i += 256) ((uint4*)pl)[i] = src[i];
    __syncthreads();

    size_t obase = ((size_t)b * CK + (size_t)c0 * 9 + k) << 12;

    for (int it = 0; it < 2; it++) {
        int pb = (w + 8 * it) * 256;
#pragma unroll
        for (int jj = 0; jj < 4; jj++) {
            int p = pb + jj * 64 + 2 * lane;       // pixel pair p, p+1
            int tb = (k << 12) + p;
            // ---- conv tap ----
            int   ci0 = g_ci[tb],     ci1 = g_ci[tb + 1];
            float cw0 = g_cw[tb],     cw1 = g_cw[tb + 1];
            // ---- deformable tap tables ----
            int4   d0 = g_idf[tb],    d1 = g_idf[tb + 1];
            float4 w0 = g_wdf[tb],    w1 = g_wdf[tb + 1];
#pragma unroll
            for (int c = 0; c < 8; c++) {
                const __half* q = pl + (c << 12);
                // conv: shifted copy (weight 0/1)
                __half v0 = (cw0 != 0.f) ? q[ci0] : __ushort_as_half((unsigned short)0);
                __half v1 = (cw1 != 0.f) ? q[ci1] : __ushort_as_half((unsigned short)0);
                *(uint32_t*)(Ac + obase + ((size_t)c * 9 << 12) + p)
                    = (uint32_t)__half_as_ushort(v0) | ((uint32_t)__half_as_ushort(v1) << 16);
                // deformable: bilinear
                float f0 = w0.x * __half2float(q[d0.x]) + w0.y * __half2float(q[d0.y])
                         + w0.z * __half2float(q[d0.z]) + w0.w * __half2float(q[d0.w]);
                float f1 = w1.x * __half2float(q[d1.x]) + w1.y * __half2float(q[d1.y])
                         + w1.z * __half2float(q[d1.z]) + w1.w * __half2float(q[d1.w]);
                *(uint32_t*)(Ad + obase + ((size_t)c * 9 << 12) + p)
                    = hpack(__float2half_rn(f0), __float2half_rn(f1));
            }
        }
    }
}

// ---------------- HMMA GEMM: A K-major [b][K][pix], B [ch][K]; D[128 pix][160 ch] ----------------
// MODE 0 (big): grid.y = asel*2+nsl; asel=0 -> A=def -> ct[0:320]; asel=1 -> A=conv -> ct[320:640]+hF.
// MODE 1 (down): A=ct (K=640) -> dn.   MODE 2 (up): A=dn (K=320) -> out = hF + scale*acc.
template<int MODE>
__global__ void __launch_bounds__(256, 2) gemm_mma(
    const __half* __restrict__ A0, const __half* __restrict__ A1,
    const __half* __restrict__ B,
    int K, const float* __restrict__ bias, float* __restrict__ hF,
    __half* __restrict__ O,
    float* __restrict__ out, const float* __restrict__ scalep)
{
    extern __shared__ char smem[];
    uint32_t sb = smem_u32(smem);
    float* fst = (float*)smem;                  // epilogue stage [80][132]
    int tid = threadIdx.x;
    int b = blockIdx.z;
    int pix0 = blockIdx.x * 128;
    int ys = blockIdx.y;
    int asel = (MODE == 0) ? (ys >> 1) : 0;
    int nsl  = (MODE == 0) ? (ys & 1) : ys;
    int NCH = K >> 5;

    const __half* Ab = ((MODE == 0 && asel) ? A1 : A0) + (size_t)b * K * HW + pix0;
    const __half* Bs = B + (size_t)(nsl * 160) * K;

    int w = tid >> 5, lane = tid & 31;
    int m0 = (w & 3) * 32;
    int ngr = w >> 2;
    int at_k = (lane & 7) + ((lane >> 4) & 1) * 8;
    int at_m = ((lane >> 3) & 1) * 8;
    int b_r = (lane & 7) + ((lane >> 4) & 1) * 8;
    int b_c = ((lane >> 3) & 1) * 16;

    float acc[2][10][4];
#pragma unroll
    for (int i = 0; i < 2; i++)
#pragma unroll
        for (int j = 0; j < 10; j++)
#pragma unroll
            for (int q = 0; q < 4; q++) acc[i][j][q] = 0.f;

    auto load_stage = [&](int ci) {
        uint32_t st = sb + (uint32_t)(ci % 3) * STGB;
        int k0 = ci << 5;
#pragma unroll
        for (int it = 0; it < 2; it++) {        // A: 32 k-rows x 256B
            int idx = tid + it * 256;
            int r = idx >> 4, j = idx & 15;
            cpa16(st + r * 272 + j * 16, Ab + (size_t)(k0 + r) * HW + j * 8);
        }
#pragma unroll
        for (int it = 0; it < 3; it++) {        // B: 160 ch-rows x 64B
            int idx = tid + it * 256;
            if (idx < 640) {
                int r = idx >> 2, j = idx & 3;
                cpa16(st + 8704 + r * 80 + j * 16, Bs + (size_t)r * K + k0 + j * 8);
            }
        }
        asm volatile("cp.async.commit_group;" ::: "memory");
    };

    load_stage(0);
    load_stage(1);
    asm volatile("cp.async.wait_group 1;" ::: "memory");
    __syncthreads();

    for (int i = 0; i < NCH; i++) {
        if (i + 2 < NCH) load_stage(i + 2);
        else asm volatile("cp.async.commit_group;" ::: "memory");
        uint32_t st = sb + (uint32_t)(i % 3) * STGB;
#pragma unroll
        for (int kk = 0; kk < 2; kk++) {
            uint32_t ah[2][4];
#pragma unroll
            for (int mf = 0; mf < 2; mf++) {
                uint32_t ad = st + (uint32_t)(kk * 16 + at_k) * 272
                                 + (uint32_t)(m0 + mf * 16 + at_m) * 2;
                LDM4T(ah[mf], ad);
            }
#pragma unroll
            for (int np = 0; np < 5; np++) {
                uint32_t bh[4];
                uint32_t bd = st + 8704 + (uint32_t)(ngr * 80 + np * 16 + b_r) * 80 + kk * 32 + b_c;
                LDM4(bh, bd);
#pragma unroll
                for (int mf = 0; mf < 2; mf++)
#pragma unroll
                    for (int h = 0; h < 2; h++)
                        MMA_F16(acc[mf][np * 2 + h], ah[mf], bh + 2 * h);
            }
        }
        asm volatile("cp.async.wait_group 1;" ::: "memory");
        __syncthreads();
    }

    float sc = (MODE == 2) ? *scalep : 0.f;
    for (int g = 0; g < 2; g++) {
        if (ngr == g) {
#pragma unroll
            for (int mf = 0; mf < 2; mf++)
#pragma unroll
                for (int nf = 0; nf < 10; nf++) {
                    int pr = m0 + mf * 16 + (lane >> 2);
                    int nc = nf * 8 + 2 * (lane & 3);
                    fst[nc * 132 + pr]           = acc[mf][nf][0];
                    fst[(nc + 1) * 132 + pr]     = acc[mf][nf][1];
                    fst[nc * 132 + pr + 8]       = acc[mf][nf][2];
                    fst[(nc + 1) * 132 + pr + 8] = acc[mf][nf][3];
                }
        }
        __syncthreads();
        int chbase = nsl * 160 + g * 80;

        if (MODE == 2) {
            for (int idx = tid; idx < 80 * 128; idx += 256) {
                int n = idx >> 7, p = idx & 127;
                size_t o = (((size_t)b * COUT + chbase + n) << 12) + pix0 + p;
                out[o] = hF[o] + sc * fst[n * 132 + p];
            }
        } else {
            if (MODE == 0 && asel == 1) {
                for (int idx = tid; idx < 80 * 128; idx += 256) {
                    int n = idx >> 7, p = idx & 127;
                    float v = fst[n * 132 + p] + __ldg(bias + chbase + n);
                    hF[(((size_t)b * COUT + chbase + n) << 12) + pix0 + p] = v;
                }
            }
            int obase = (MODE == 0) ? (asel * 320 + chbase) : chbase;
            int odim  = (MODE == 0) ? CAT2 : COUT;
            for (int idx = tid; idx < 80 * 64; idx += 256) {
                int n = idx >> 6, p2 = idx & 63;
                float v0 = fst[n * 132 + p2 * 2];
                float v1 = fst[n * 132 + p2 * 2 + 1];
                if (MODE == 0) {
                    float bv = __ldg(bias + chbase + n);
                    v0 += bv; v1 += bv;
                }
                *(uint32_t*)(O + (((size_t)b * odim + obase + n) << 12) + pix0 + p2 * 2)
                    = hpack(__float2half_rn(v0), __float2half_rn(v1));
            }
        }
        __syncthreads();
    }
}

// ---------------- launch ----------------
extern "C" void kernel_launch(void* const* d_in, const int* in_sizes, int n_in,
                              void* d_out, int out_size) {
    const float* x      = (const float*)d_in[0];
    const float* weight = (const float*)d_in[1];
    const float* bias   = (const float*)d_in[2];
    const float* w_down = (const float*)d_in[3];
    const float* w_up   = (const float*)d_in[4];
    const float* scale  = (const float*)d_in[5];
    const float* offset = (const float*)d_in[6];
    float* out = (float*)d_out;

    __half *xh, *Ac, *Ad, *wt, *wd, *wu, *ct, *dn;
    float *hF;
    cudaGetSymbolAddress((void**)&xh, g_xh);
    cudaGetSymbolAddress((void**)&Ac, g_Ac); cudaGetSymbolAddress((void**)&Ad, g_Ad);
    cudaGetSymbolAddress((void**)&wt, g_wt); cudaGetSymbolAddress((void**)&wd, g_wd);
    cudaGetSymbolAddress((void**)&wu, g_wu);
    cudaGetSymbolAddress((void**)&ct, g_ct); cudaGetSymbolAddress((void**)&dn, g_dn);
    cudaGetSymbolAddress((void**)&hF, g_hF);

    cudaFuncSetAttribute(gemm_mma<0>, cudaFuncAttributeMaxDynamicSharedMemorySize, SMEMB);
    cudaFuncSetAttribute(gemm_mma<1>, cudaFuncAttributeMaxDynamicSharedMemorySize, SMEMB);
    cudaFuncSetAttribute(gemm_mma<2>, cudaFuncAttributeMaxDynamicSharedMemorySize, SMEMB);

    // #1, #2
    precompute<<<(9 * HW + 255) / 256, 256>>>(offset);
    prep_w<<<(NW1 + NW2 + NW3 + 255) / 256, 256>>>(weight, w_down, w_up, wt, wd, wu);
    // #3: x -> fp16
    to_xh<<<(BATCH * CIN * HW) / 2048, 256>>>(x, xh);
    // #4 (profiled): per-tap im2col, conflict-free
    im2col_k<<<dim3(40, 9, BATCH), 256>>>(xh, Ac, Ad);
    // #5: big dual GEMM
    gemm_mma<0><<<dim3(HW / 128, 4, BATCH), 256, SMEMB>>>(
        Ad, Ac, wt, CK, bias, hF, ct, nullptr, nullptr);
    // #6: down
    gemm_mma<1><<<dim3(HW / 128, 2, BATCH), 256, SMEMB>>>(
        ct, nullptr, wd, CAT2, nullptr, nullptr, dn, nullptr, nullptr);
    // #7: up + residual
    gemm_mma<2><<<dim3(HW / 128, 2, BATCH), 256, SMEMB>>>(
        dn, nullptr, wu, COUT, nullptr, hF, nullptr, out, scale);
}

// round 13
// speedup vs baseline: 1.7899x; 1.0270x over previous
#include <cuda_runtime.h>
#include <cuda_fp16.h>
#include <cstdint>

#define BATCH 4
#define CIN   320
#define COUT  320
#define HW    4096
#define CK    2880           // K = c*9 + k
#define CAT2  640
// GEMM stage: A 32 rows x 272B = 8704 ; B 160 rows x 80B = 12800 ; total 21504, 3 stages
#define STGB  21504
#define SMEMB 64512

// ---------------- device scratch (A/ct/dn K-major: [b][K][pix]) ----------------
__device__ __half g_xh[(size_t)BATCH*CIN*HW];
__device__ __half g_Ac[(size_t)BATCH*CK*HW];
__device__ __half g_Ad[(size_t)BATCH*CK*HW];
__device__ __half g_wt[COUT*CK];
__device__ __half g_wd[COUT*CAT2];
__device__ __half g_wu[COUT*COUT];
__device__ __half g_ct[(size_t)BATCH*CAT2*HW];
__device__ __half g_dn[(size_t)BATCH*COUT*HW];
__device__ float  g_hF[(size_t)BATCH*COUT*HW];
__device__ int4   g_idf[9*HW];
__device__ float4 g_wdf[9*HW];

// ---------------- helpers ----------------
__device__ __forceinline__ uint32_t smem_u32(const void* p) {
    uint32_t a;
    asm("{ .reg .u64 t; cvta.to.shared.u64 t, %1; cvt.u32.u64 %0, t; }" : "=r"(a) : "l"(p));
    return a;
}
__device__ __forceinline__ void cpa16(uint32_t dst, const void* src) {
    asm volatile("cp.async.cg.shared.global [%0], [%1], 16;" :: "r"(dst), "l"(src));
}
#define LDM4(r, addr) \
    asm volatile("ldmatrix.sync.aligned.m8n8.x4.shared.b16 {%0,%1,%2,%3}, [%4];" \
        : "=r"((r)[0]), "=r"((r)[1]), "=r"((r)[2]), "=r"((r)[3]) : "r"(addr))
#define LDM4T(r, addr) \
    asm volatile("ldmatrix.sync.aligned.m8n8.x4.trans.shared.b16 {%0,%1,%2,%3}, [%4];" \
        : "=r"((r)[0]), "=r"((r)[1]), "=r"((r)[2]), "=r"((r)[3]) : "r"(addr))
#define MMA_F16(c, a, bq) \
    asm volatile("mma.sync.aligned.m16n8k16.row.col.f32.f16.f16.f32 " \
        "{%0,%1,%2,%3}, {%4,%5,%6,%7}, {%8,%9}, {%0,%1,%2,%3};" \
        : "+f"((c)[0]), "+f"((c)[1]), "+f"((c)[2]), "+f"((c)[3]) \
        : "r"((a)[0]), "r"((a)[1]), "r"((a)[2]), "r"((a)[3]), "r"((bq)[0]), "r"((bq)[1]))

__device__ __forceinline__ uint32_t hpack(__half a, __half b) {
    return (uint32_t)__half_as_ushort(a) | ((uint32_t)__half_as_ushort(b) << 16);
}

// ---------------- launch #1: unified prep (weights + x->fp16 + bilinear tables) ----------------
#define NW1 (COUT*CK)
#define NW2 (COUT*CAT2)
#define NW3 (COUT*COUT)
#define PREP_W4   ((NW1 + NW2 + NW3) / 4)            // 307200 threads, 4 elems each
#define PREP_XH   (BATCH * CIN * HW / 8)             // 655360 threads, 8 elems each
#define PREP_TBL  (9 * HW)                           // 36864 threads
#define PREP_TOT  (PREP_W4 + PREP_XH + PREP_TBL)     // 999424 = 3904 * 256

__global__ void prep_all(const float* __restrict__ w, const float* __restrict__ wdn,
                         const float* __restrict__ wup, const float* __restrict__ scalep,
                         const float* __restrict__ x, const float* __restrict__ off,
                         __half* wt, __half* wd, __half* wu, __half* xh) {
    int i = blockIdx.x * 256 + threadIdx.x;
    if (i < PREP_W4) {
        int j = i * 4;
        if (j < NW1) {
            float4 v = *(const float4*)(w + j);
            *(uint2*)(wt + j) = make_uint2(hpack(__float2half_rn(v.x), __float2half_rn(v.y)),
                                           hpack(__float2half_rn(v.z), __float2half_rn(v.w)));
        } else if (j < NW1 + NW2) {
            int jj = j - NW1;
            float4 v = *(const float4*)(wdn + jj);
            *(uint2*)(wd + jj) = make_uint2(hpack(__float2half_rn(v.x), __float2half_rn(v.y)),
                                            hpack(__float2half_rn(v.z), __float2half_rn(v.w)));
        } else {
            int jj = j - NW1 - NW2;
            float sc = *scalep;
            float4 v = *(const float4*)(wup + jj);
            *(uint2*)(wu + jj) = make_uint2(hpack(__float2half_rn(v.x * sc), __float2half_rn(v.y * sc)),
                                            hpack(__float2half_rn(v.z * sc), __float2half_rn(v.w * sc)));
        }
    } else if (i < PREP_W4 + PREP_XH) {
        size_t j = (size_t)(i - PREP_W4) * 8;
        float4 a = *(const float4*)(x + j);
        float4 b2 = *(const float4*)(x + j + 4);
        uint4 o;
        o.x = hpack(__float2half_rn(a.x), __float2half_rn(a.y));
        o.y = hpack(__float2half_rn(a.z), __float2half_rn(a.w));
        o.z = hpack(__float2half_rn(b2.x), __float2half_rn(b2.y));
        o.w = hpack(__float2half_rn(b2.z), __float2half_rn(b2.w));
        *(uint4*)(xh + j) = o;
    } else {
        int t = i - PREP_W4 - PREP_XH;
        int k = t >> 12, p = t & 4095;
        int r = p >> 6, c = p & 63;
        int rr = r + k / 3 - 1, qq = c + k % 3 - 1;
        float dy = off[((k*2+0) << 12) + p];
        float dx = off[((k*2+1) << 12) + p];
        float py = (float)rr + dy, px = (float)qq + dx;
        float y0f = floorf(py), x0f = floorf(px);
        int y0 = (int)y0f, x0 = (int)x0f;
        float wy = py - y0f, wx = px - x0f;
        float wv[4] = { (1.f-wy)*(1.f-wx), (1.f-wy)*wx, wy*(1.f-wx), wy*wx };
        int   idx[4]; float wgt[4];
#pragma unroll
        for (int j = 0; j < 4; j++) {
            int yy = y0 + (j >> 1), xx = x0 + (j & 1);
            bool ok = (yy >= 0 && yy < 64 && xx >= 0 && xx < 64);
            idx[j] = (min(max(yy,0),63) << 6) + min(max(xx,0),63);
            wgt[j] = ok ? wv[j] : 0.f;
        }
        g_idf[t] = make_int4(idx[0], idx[1], idx[2], idx[3]);
        g_wdf[t] = make_float4(wgt[0], wgt[1], wgt[2], wgt[3]);
    }
}

// ---------------- launch #2: per-tap im2col, conflict-free lanes ----------------
// grid (40 c-blocks, 9 taps, 4 batch). Lane owns pixel pair pb + 2*lane + 64*jj.
// Conv tap computed arithmetically (no tables); bilinear from g_idf/g_wdf.
__global__ __launch_bounds__(256, 2) void im2col_k(
    const __half* __restrict__ xh,
    __half* __restrict__ Ac, __half* __restrict__ Ad)
{
    __shared__ __half pl[8 * 4096];     // 64KB
    int b = blockIdx.z, k = blockIdx.y, c0 = blockIdx.x * 8;
    int tid = threadIdx.x;
    int w = tid >> 5, lane = tid & 31;
    int dr = k / 3 - 1, dc = k % 3 - 1;
    const uint4* src = (const uint4*)(xh + (((size_t)b * CIN + c0) << 12));
    for (int i = tid; i < 4096; i += 256) ((uint4*)pl)[i] = src[i];
    __syncthreads();

    size_t obase = ((size_t)b * CK + (size_t)c0 * 9 + k) << 12;

    for (int it = 0; it < 2; it++) {
        int pb = (w + 8 * it) * 256;
#pragma unroll
        for (int jj = 0; jj < 4; jj++) {
            int p = pb + jj * 64 + 2 * lane;       // pixel pair p, p+1 (same image row)
            // ---- conv tap (arithmetic) ----
            int rr = (p >> 6) + dr;
            int cc0 = (p & 63) + dc;
            bool rok = (unsigned)rr < 64u;
            bool ok0 = rok && (unsigned)cc0 < 64u;
            bool ok1 = rok && (unsigned)(cc0 + 1) < 64u;
            int ci0 = ok0 ? ((rr << 6) + cc0) : 0;
            int ci1 = ok1 ? ((rr << 6) + cc0 + 1) : 0;
            // ---- deformable tap tables ----
            int tb = (k << 12) + p;
            int4   d0 = g_idf[tb],    d1 = g_idf[tb + 1];
            float4 w0 = g_wdf[tb],    w1 = g_wdf[tb + 1];
#pragma unroll
            for (int c = 0; c < 8; c++) {
                const __half* q = pl + (c << 12);
                __half v0 = ok0 ? q[ci0] : __ushort_as_half((unsigned short)0);
                __half v1 = ok1 ? q[ci1] : __ushort_as_half((unsigned short)0);
                *(uint32_t*)(Ac + obase + ((size_t)c * 9 << 12) + p)
                    = (uint32_t)__half_as_ushort(v0) | ((uint32_t)__half_as_ushort(v1) << 16);
                float f0 = w0.x * __half2float(q[d0.x]) + w0.y * __half2float(q[d0.y])
                         + w0.z * __half2float(q[d0.z]) + w0.w * __half2float(q[d0.w]);
                float f1 = w1.x * __half2float(q[d1.x]) + w1.y * __half2float(q[d1.y])
                         + w1.z * __half2float(q[d1.z]) + w1.w * __half2float(q[d1.w]);
                *(uint32_t*)(Ad + obase + ((size_t)c * 9 << 12) + p)
                    = hpack(__float2half_rn(f0), __float2half_rn(f1));
            }
        }
    }
}

// ---------------- HMMA GEMM: A K-major [b][K][pix], B [ch][K]; D[128 pix][160 ch] ----------------
// MODE 0 (big): grid.y = asel*2+nsl; asel=0 -> A=def -> ct[0:320]; asel=1 -> A=conv -> ct[320:640]+hF.
// MODE 1 (down): A=ct (K=640) -> dn.   MODE 2 (up): A=dn (K=320) -> out = hF + acc (scale pre-folded).
template<int MODE>
__global__ void __launch_bounds__(256, 2) gemm_mma(
    const __half* __restrict__ A0, const __half* __restrict__ A1,
    const __half* __restrict__ B,
    int K, const float* __restrict__ bias, float* __restrict__ hF,
    __half* __restrict__ O,
    float* __restrict__ out)
{
    extern __shared__ char smem[];
    uint32_t sb = smem_u32(smem);
    float* fst = (float*)smem;                  // epilogue stage [80][132]
    int tid = threadIdx.x;
    int b = blockIdx.z;
    int pix0 = blockIdx.x * 128;
    int ys = blockIdx.y;
    int asel = (MODE == 0) ? (ys >> 1) : 0;
    int nsl  = (MODE == 0) ? (ys & 1) : ys;
    int NCH = K >> 5;

    const __half* Ab = ((MODE == 0 && asel) ? A1 : A0) + (size_t)b * K * HW + pix0;
    const __half* Bs = B + (size_t)(nsl * 160) * K;

    int w = tid >> 5, lane = tid & 31;
    int m0 = (w & 3) * 32;
    int ngr = w >> 2;
    int at_k = (lane & 7) + ((lane >> 4) & 1) * 8;
    int at_m = ((lane >> 3) & 1) * 8;
    int b_r = (lane & 7) + ((lane >> 4) & 1) * 8;
    int b_c = ((lane >> 3) & 1) * 16;

    float acc[2][10][4];
#pragma unroll
    for (int i = 0; i < 2; i++)
#pragma unroll
        for (int j = 0; j < 10; j++)
#pragma unroll
            for (int q = 0; q < 4; q++) acc[i][j][q] = 0.f;

    auto load_stage = [&](int ci) {
        uint32_t st = sb + (uint32_t)(ci % 3) * STGB;
        int k0 = ci << 5;
#pragma unroll
        for (int it = 0; it < 2; it++) {        // A: 32 k-rows x 256B
            int idx = tid + it * 256;
            int r = idx >> 4, j = idx & 15;
            cpa16(st + r * 272 + j * 16, Ab + (size_t)(k0 + r) * HW + j * 8);
        }
#pragma unroll
        for (int it = 0; it < 3; it++) {        // B: 160 ch-rows x 64B
            int idx = tid + it * 256;
            if (idx < 640) {
                int r = idx >> 2, j = idx & 3;
                cpa16(st + 8704 + r * 80 + j * 16, Bs + (size_t)r * K + k0 + j * 8);
            }
        }
        asm volatile("cp.async.commit_group;" ::: "memory");
    };

    load_stage(0);
    load_stage(1);
    asm volatile("cp.async.wait_group 1;" ::: "memory");
    __syncthreads();

    for (int i = 0; i < NCH; i++) {
        if (i + 2 < NCH) load_stage(i + 2);
        else asm volatile("cp.async.commit_group;" ::: "memory");
        uint32_t st = sb + (uint32_t)(i % 3) * STGB;
#pragma unroll
        for (int kk = 0; kk < 2; kk++) {
            uint32_t ah[2][4];
#pragma unroll
            for (int mf = 0; mf < 2; mf++) {
                uint32_t ad = st + (uint32_t)(kk * 16 + at_k) * 272
                                 + (uint32_t)(m0 + mf * 16 + at_m) * 2;
                LDM4T(ah[mf], ad);
            }
#pragma unroll
            for (int np = 0; np < 5; np++) {
                uint32_t bh[4];
                uint32_t bd = st + 8704 + (uint32_t)(ngr * 80 + np * 16 + b_r) * 80 + kk * 32 + b_c;
                LDM4(bh, bd);
#pragma unroll
                for (int mf = 0; mf < 2; mf++)
#pragma unroll
                    for (int h = 0; h < 2; h++)
                        MMA_F16(acc[mf][np * 2 + h], ah[mf], bh + 2 * h);
            }
        }
        asm volatile("cp.async.wait_group 1;" ::: "memory");
        __syncthreads();
    }

    for (int g = 0; g < 2; g++) {
        if (ngr == g) {
#pragma unroll
            for (int mf = 0; mf < 2; mf++)
#pragma unroll
                for (int nf = 0; nf < 10; nf++) {
                    int pr = m0 + mf * 16 + (lane >> 2);
                    int nc = nf * 8 + 2 * (lane & 3);
                    fst[nc * 132 + pr]           = acc[mf][nf][0];
                    fst[(nc + 1) * 132 + pr]     = acc[mf][nf][1];
                    fst[nc * 132 + pr + 8]       = acc[mf][nf][2];
                    fst[(nc + 1) * 132 + pr + 8] = acc[mf][nf][3];
                }
        }
        __syncthreads();
        int chbase = nsl * 160 + g * 80;

        if (MODE == 2) {
            for (int idx = tid; idx < 80 * 128; idx += 256) {
                int n = idx >> 7, p = idx & 127;
                size_t o = (((size_t)b * COUT + chbase + n) << 12) + pix0 + p;
                out[o] = hF[o] + fst[n * 132 + p];
            }
        } else {
            if (MODE == 0 && asel == 1) {
                for (int idx = tid; idx < 80 * 128; idx += 256) {
                    int n = idx >> 7, p = idx & 127;
                    float v = fst[n * 132 + p] + __ldg(bias + chbase + n);
                    hF[(((size_t)b * COUT + chbase + n) << 12) + pix0 + p] = v;
                }
            }
            int obase = (MODE == 0) ? (asel * 320 + chbase) : chbase;
            int odim  = (MODE == 0) ? CAT2 : COUT;
            for (int idx = tid; idx < 80 * 64; idx += 256) {
                int n = idx >> 6, p2 = idx & 63;
                float v0 = fst[n * 132 + p2 * 2];
                float v1 = fst[n * 132 + p2 * 2 + 1];
                if (MODE == 0) {
                    float bv = __ldg(bias + chbase + n);
                    v0 += bv; v1 += bv;
                }
                *(uint32_t*)(O + (((size_t)b * odim + obase + n) << 12) + pix0 + p2 * 2)
                    = hpack(__float2half_rn(v0), __float2half_rn(v1));
            }
        }
        __syncthreads();
    }
}

// ---------------- launch ----------------
extern "C" void kernel_launch(void* const* d_in, const int* in_sizes, int n_in,
                              void* d_out, int out_size) {
    const float* x      = (const float*)d_in[0];
    const float* weight = (const float*)d_in[1];
    const float* bias   = (const float*)d_in[2];
    const float* w_down = (const float*)d_in[3];
    const float* w_up   = (const float*)d_in[4];
    const float* scale  = (const float*)d_in[5];
    const float* offset = (const float*)d_in[6];
    float* out = (float*)d_out;

    __half *xh, *Ac, *Ad, *wt, *wd, *wu, *ct, *dn;
    float *hF;
    cudaGetSymbolAddress((void**)&xh, g_xh);
    cudaGetSymbolAddress((void**)&Ac, g_Ac); cudaGetSymbolAddress((void**)&Ad, g_Ad);
    cudaGetSymbolAddress((void**)&wt, g_wt); cudaGetSymbolAddress((void**)&wd, g_wd);
    cudaGetSymbolAddress((void**)&wu, g_wu);
    cudaGetSymbolAddress((void**)&ct, g_ct); cudaGetSymbolAddress((void**)&dn, g_dn);
    cudaGetSymbolAddress((void**)&hF, g_hF);

    cudaFuncSetAttribute(gemm_mma<0>, cudaFuncAttributeMaxDynamicSharedMemorySize, SMEMB);
    cudaFuncSetAttribute(gemm_mma<1>, cudaFuncAttributeMaxDynamicSharedMemorySize, SMEMB);
    cudaFuncSetAttribute(gemm_mma<2>, cudaFuncAttributeMaxDynamicSharedMemorySize, SMEMB);

    // #1: unified prep
    prep_all<<<PREP_TOT / 256, 256>>>(weight, w_down, w_up, scale, x, offset,
                                      wt, wd, wu, xh);
    // #2: per-tap im2col
    im2col_k<<<dim3(40, 9, BATCH), 256>>>(xh, Ac, Ad);
    // #3: big dual GEMM
    gemm_mma<0><<<dim3(HW / 128, 4, BATCH), 256, SMEMB>>>(
        Ad, Ac, wt, CK, bias, hF, ct, nullptr);
    // #4 (profiled): down
    gemm_mma<1><<<dim3(HW / 128, 2, BATCH), 256, SMEMB>>>(
        ct, nullptr, wd, CAT2, nullptr, nullptr, dn, nullptr);
    // #5: up + residual (scale folded into wu)
    gemm_mma<2><<<dim3(HW / 128, 2, BATCH), 256, SMEMB>>>(
        dn, nullptr, wu, COUT, nullptr, hF, nullptr, out);
}

// round 14
// speedup vs baseline: 1.8153x; 1.0142x over previous
#include <cuda_runtime.h>
#include <cuda_fp16.h>
#include <cstdint>

#define BATCH 4
#define CIN   320
#define COUT  320
#define HW    4096
#define CK    2880           // K = c*9 + k
#define CAT2  640
// GEMM stage: A 32 rows x 272B = 8704 ; B 160 rows x 80B = 12800 ; total 21504, 3 stages
#define STGB  21504
#define SMEMB 64512

// ---------------- device scratch (A/ct/dn K-major: [b][K][pix]) ----------------
__device__ __half g_xh[(size_t)BATCH*CIN*HW];
__device__ __half g_Ac[(size_t)BATCH*CK*HW];
__device__ __half g_Ad[(size_t)BATCH*CK*HW];
__device__ __half g_wt[COUT*CK];
__device__ __half g_wd[COUT*CAT2];
__device__ __half g_wu[COUT*COUT];
__device__ __half g_ct[(size_t)BATCH*CAT2*HW];
__device__ __half g_dn[(size_t)BATCH*COUT*HW];
__device__ float  g_hF[(size_t)BATCH*COUT*HW];
__device__ int4   g_idf[9*HW];
__device__ float4 g_wdf[9*HW];

// ---------------- helpers ----------------
__device__ __forceinline__ uint32_t smem_u32(const void* p) {
    uint32_t a;
    asm("{ .reg .u64 t; cvta.to.shared.u64 t, %1; cvt.u32.u64 %0, t; }" : "=r"(a) : "l"(p));
    return a;
}
__device__ __forceinline__ void cpa16(uint32_t dst, const void* src) {
    asm volatile("cp.async.cg.shared.global [%0], [%1], 16;" :: "r"(dst), "l"(src));
}
#define LDM4(r, addr) \
    asm volatile("ldmatrix.sync.aligned.m8n8.x4.shared.b16 {%0,%1,%2,%3}, [%4];" \
        : "=r"((r)[0]), "=r"((r)[1]), "=r"((r)[2]), "=r"((r)[3]) : "r"(addr))
#define LDM4T(r, addr) \
    asm volatile("ldmatrix.sync.aligned.m8n8.x4.trans.shared.b16 {%0,%1,%2,%3}, [%4];" \
        : "=r"((r)[0]), "=r"((r)[1]), "=r"((r)[2]), "=r"((r)[3]) : "r"(addr))
#define MMA_F16(c, a, bq) \
    asm volatile("mma.sync.aligned.m16n8k16.row.col.f32.f16.f16.f32 " \
        "{%0,%1,%2,%3}, {%4,%5,%6,%7}, {%8,%9}, {%0,%1,%2,%3};" \
        : "+f"((c)[0]), "+f"((c)[1]), "+f"((c)[2]), "+f"((c)[3]) \
        : "r"((a)[0]), "r"((a)[1]), "r"((a)[2]), "r"((a)[3]), "r"((bq)[0]), "r"((bq)[1]))

__device__ __forceinline__ uint32_t hpack(__half a, __half b) {
    return (uint32_t)__half_as_ushort(a) | ((uint32_t)__half_as_ushort(b) << 16);
}

// ---------------- launch #1: unified prep (weights + x->fp16 + bilinear tables) ----------------
#define NW1 (COUT*CK)
#define NW2 (COUT*CAT2)
#define NW3 (COUT*COUT)
#define PREP_W4   ((NW1 + NW2 + NW3) / 4)
#define PREP_XH   (BATCH * CIN * HW / 8)
#define PREP_TBL  (9 * HW)
#define PREP_TOT  (PREP_W4 + PREP_XH + PREP_TBL)

__global__ void prep_all(const float* __restrict__ w, const float* __restrict__ wdn,
                         const float* __restrict__ wup, const float* __restrict__ scalep,
                         const float* __restrict__ x, const float* __restrict__ off,
                         __half* wt, __half* wd, __half* wu, __half* xh) {
    int i = blockIdx.x * 256 + threadIdx.x;
    if (i < PREP_W4) {
        int j = i * 4;
        if (j < NW1) {
            float4 v = *(const float4*)(w + j);
            *(uint2*)(wt + j) = make_uint2(hpack(__float2half_rn(v.x), __float2half_rn(v.y)),
                                           hpack(__float2half_rn(v.z), __float2half_rn(v.w)));
        } else if (j < NW1 + NW2) {
            int jj = j - NW1;
            float4 v = *(const float4*)(wdn + jj);
            *(uint2*)(wd + jj) = make_uint2(hpack(__float2half_rn(v.x), __float2half_rn(v.y)),
                                            hpack(__float2half_rn(v.z), __float2half_rn(v.w)));
        } else {
            int jj = j - NW1 - NW2;
            float sc = *scalep;
            float4 v = *(const float4*)(wup + jj);
            *(uint2*)(wu + jj) = make_uint2(hpack(__float2half_rn(v.x * sc), __float2half_rn(v.y * sc)),
                                            hpack(__float2half_rn(v.z * sc), __float2half_rn(v.w * sc)));
        }
    } else if (i < PREP_W4 + PREP_XH) {
        size_t j = (size_t)(i - PREP_W4) * 8;
        float4 a = *(const float4*)(x + j);
        float4 b2 = *(const float4*)(x + j + 4);
        uint4 o;
        o.x = hpack(__float2half_rn(a.x), __float2half_rn(a.y));
        o.y = hpack(__float2half_rn(a.z), __float2half_rn(a.w));
        o.z = hpack(__float2half_rn(b2.x), __float2half_rn(b2.y));
        o.w = hpack(__float2half_rn(b2.z), __float2half_rn(b2.w));
        *(uint4*)(xh + j) = o;
    } else {
        int t = i - PREP_W4 - PREP_XH;
        int k = t >> 12, p = t & 4095;
        int r = p >> 6, c = p & 63;
        int rr = r + k / 3 - 1, qq = c + k % 3 - 1;
        float dy = off[((k*2+0) << 12) + p];
        float dx = off[((k*2+1) << 12) + p];
        float py = (float)rr + dy, px = (float)qq + dx;
        float y0f = floorf(py), x0f = floorf(px);
        int y0 = (int)y0f, x0 = (int)x0f;
        float wy = py - y0f, wx = px - x0f;
        float wv[4] = { (1.f-wy)*(1.f-wx), (1.f-wy)*wx, wy*(1.f-wx), wy*wx };
        int   idx[4]; float wgt[4];
#pragma unroll
        for (int j = 0; j < 4; j++) {
            int yy = y0 + (j >> 1), xx = x0 + (j & 1);
            bool ok = (yy >= 0 && yy < 64 && xx >= 0 && xx < 64);
            idx[j] = (min(max(yy,0),63) << 6) + min(max(xx,0),63);
            wgt[j] = ok ? wv[j] : 0.f;
        }
        g_idf[t] = make_int4(idx[0], idx[1], idx[2], idx[3]);
        g_wdf[t] = make_float4(wgt[0], wgt[1], wgt[2], wgt[3]);
    }
}

// ---------------- launch #2: per-tap im2col, conflict-free lanes ----------------
__global__ __launch_bounds__(256, 2) void im2col_k(
    const __half* __restrict__ xh,
    __half* __restrict__ Ac, __half* __restrict__ Ad)
{
    __shared__ __half pl[8 * 4096];     // 64KB
    int b = blockIdx.z, k = blockIdx.y, c0 = blockIdx.x * 8;
    int tid = threadIdx.x;
    int w = tid >> 5, lane = tid & 31;
    int dr = k / 3 - 1, dc = k % 3 - 1;
    const uint4* src = (const uint4*)(xh + (((size_t)b * CIN + c0) << 12));
    for (int i = tid; i < 4096; i += 256) ((uint4*)pl)[i] = src[i];
    __syncthreads();

    size_t obase = ((size_t)b * CK + (size_t)c0 * 9 + k) << 12;

    for (int it = 0; it < 2; it++) {
        int pb = (w + 8 * it) * 256;
#pragma unroll
        for (int jj = 0; jj < 4; jj++) {
            int p = pb + jj * 64 + 2 * lane;
            int rr = (p >> 6) + dr;
            int cc0 = (p & 63) + dc;
            bool rok = (unsigned)rr < 64u;
            bool ok0 = rok && (unsigned)cc0 < 64u;
            bool ok1 = rok && (unsigned)(cc0 + 1) < 64u;
            int ci0 = ok0 ? ((rr << 6) + cc0) : 0;
            int ci1 = ok1 ? ((rr << 6) + cc0 + 1) : 0;
            int tb = (k << 12) + p;
            int4   d0 = g_idf[tb],    d1 = g_idf[tb + 1];
            float4 w0 = g_wdf[tb],    w1 = g_wdf[tb + 1];
#pragma unroll
            for (int c = 0; c < 8; c++) {
                const __half* q = pl + (c << 12);
                __half v0 = ok0 ? q[ci0] : __ushort_as_half((unsigned short)0);
                __half v1 = ok1 ? q[ci1] : __ushort_as_half((unsigned short)0);
                *(uint32_t*)(Ac + obase + ((size_t)c * 9 << 12) + p)
                    = (uint32_t)__half_as_ushort(v0) | ((uint32_t)__half_as_ushort(v1) << 16);
                float f0 = w0.x * __half2float(q[d0.x]) + w0.y * __half2float(q[d0.y])
                         + w0.z * __half2float(q[d0.z]) + w0.w * __half2float(q[d0.w]);
                float f1 = w1.x * __half2float(q[d1.x]) + w1.y * __half2float(q[d1.y])
                         + w1.z * __half2float(q[d1.z]) + w1.w * __half2float(q[d1.w]);
                *(uint32_t*)(Ad + obase + ((size_t)c * 9 << 12) + p)
                    = hpack(__float2half_rn(f0), __float2half_rn(f1));
            }
        }
    }
}

// ---------------- HMMA GEMM, fragment-pipelined mainloop ----------------
// MODE 0 (big): grid.y = asel*2+nsl; asel=0 -> A=def -> ct[0:320]; asel=1 -> A=conv -> ct[320:640]+hF.
// MODE 1 (down): A=ct (K=640) -> dn.   MODE 2 (up): A=dn (K=320) -> out = hF + acc (scale pre-folded).
template<int MODE>
__global__ void __launch_bounds__(256, 2) gemm_mma(
    const __half* __restrict__ A0, const __half* __restrict__ A1,
    const __half* __restrict__ B,
    int K, const float* __restrict__ bias, float* __restrict__ hF,
    __half* __restrict__ O,
    float* __restrict__ out)
{
    extern __shared__ char smem[];
    uint32_t sb = smem_u32(smem);
    float* fst = (float*)smem;                  // epilogue stage [80][132]
    int tid = threadIdx.x;
    int b = blockIdx.z;
    int pix0 = blockIdx.x * 128;
    int ys = blockIdx.y;
    int asel = (MODE == 0) ? (ys >> 1) : 0;
    int nsl  = (MODE == 0) ? (ys & 1) : ys;
    int NCH = K >> 5;

    const __half* Ab = ((MODE == 0 && asel) ? A1 : A0) + (size_t)b * K * HW + pix0;
    const __half* Bs = B + (size_t)(nsl * 160) * K;

    int w = tid >> 5, lane = tid & 31;
    int m0 = (w & 3) * 32;
    int ngr = w >> 2;
    int at_k = (lane & 7) + ((lane >> 4) & 1) * 8;
    int at_m = ((lane >> 3) & 1) * 8;
    int b_r = (lane & 7) + ((lane >> 4) & 1) * 8;
    int b_c = ((lane >> 3) & 1) * 16;

    float acc[2][10][4];
#pragma unroll
    for (int i = 0; i < 2; i++)
#pragma unroll
        for (int j = 0; j < 10; j++)
#pragma unroll
            for (int q = 0; q < 4; q++) acc[i][j][q] = 0.f;

    auto load_stage = [&](int ci) {
        uint32_t st = sb + (uint32_t)(ci % 3) * STGB;
        int k0 = ci << 5;
#pragma unroll
        for (int it = 0; it < 2; it++) {        // A: 32 k-rows x 256B
            int idx = tid + it * 256;
            int r = idx >> 4, j = idx & 15;
            cpa16(st + r * 272 + j * 16, Ab + (size_t)(k0 + r) * HW + j * 8);
        }
#pragma unroll
        for (int it = 0; it < 3; it++) {        // B: 160 ch-rows x 64B
            int idx = tid + it * 256;
            if (idx < 640) {
                int r = idx >> 2, j = idx & 3;
                cpa16(st + 8704 + r * 80 + j * 16, Bs + (size_t)r * K + k0 + j * 8);
            }
        }
        asm volatile("cp.async.commit_group;" ::: "memory");
    };

    load_stage(0);
    load_stage(1);
    asm volatile("cp.async.wait_group 1;" ::: "memory");
    __syncthreads();

    for (int i = 0; i < NCH; i++) {
        if (i + 2 < NCH) load_stage(i + 2);
        else asm volatile("cp.async.commit_group;" ::: "memory");
        uint32_t st = sb + (uint32_t)(i % 3) * STGB;

        uint32_t ah[2][2][4];       // [kk][mf]
        uint32_t bh[2][4];          // double buffer over t
        // preload ah(kk=0) and bh(t=0)
#pragma unroll
        for (int mf = 0; mf < 2; mf++) {
            uint32_t ad = st + (uint32_t)at_k * 272 + (uint32_t)(m0 + mf * 16 + at_m) * 2;
            LDM4T(ah[0][mf], ad);
        }
        {
            uint32_t bd = st + 8704 + (uint32_t)(ngr * 80 + b_r) * 80 + b_c;
            LDM4(bh[0], bd);
        }
#pragma unroll
        for (int t = 0; t < 10; t++) {
            const int kk = t / 5, np = t % 5;
            if (t == 3) {           // prefetch ah for kk=1
#pragma unroll
                for (int mf = 0; mf < 2; mf++) {
                    uint32_t ad = st + (uint32_t)(16 + at_k) * 272
                                     + (uint32_t)(m0 + mf * 16 + at_m) * 2;
                    LDM4T(ah[1][mf], ad);
                }
            }
            if (t < 9) {            // prefetch bh for t+1
                const int kk1 = (t + 1) / 5, np1 = (t + 1) % 5;
                uint32_t bd = st + 8704 + (uint32_t)(ngr * 80 + np1 * 16 + b_r) * 80
                                 + kk1 * 32 + b_c;
                LDM4(bh[(t + 1) & 1], bd);
            }
#pragma unroll
            for (int mf = 0; mf < 2; mf++)
#pragma unroll
                for (int h = 0; h < 2; h++)
                    MMA_F16(acc[mf][np * 2 + h], ah[kk][mf], bh[t & 1] + 2 * h);
        }
        asm volatile("cp.async.wait_group 1;" ::: "memory");
        __syncthreads();
    }

    for (int g = 0; g < 2; g++) {
        if (ngr == g) {
#pragma unroll
            for (int mf = 0; mf < 2; mf++)
#pragma unroll
                for (int nf = 0; nf < 10; nf++) {
                    int pr = m0 + mf * 16 + (lane >> 2);
                    int nc = nf * 8 + 2 * (lane & 3);
                    fst[nc * 132 + pr]           = acc[mf][nf][0];
                    fst[(nc + 1) * 132 + pr]     = acc[mf][nf][1];
                    fst[nc * 132 + pr + 8]       = acc[mf][nf][2];
                    fst[(nc + 1) * 132 + pr + 8] = acc[mf][nf][3];
                }
        }
        __syncthreads();
        int chbase = nsl * 160 + g * 80;

        if (MODE == 2) {
            for (int idx = tid; idx < 80 * 128; idx += 256) {
                int n = idx >> 7, p = idx & 127;
                size_t o = (((size_t)b * COUT + chbase + n) << 12) + pix0 + p;
                out[o] = hF[o] + fst[n * 132 + p];
            }
        } else {
            if (MODE == 0 && asel == 1) {
                for (int idx = tid; idx < 80 * 128; idx += 256) {
                    int n = idx >> 7, p = idx & 127;
                    float v = fst[n * 132 + p] + __ldg(bias + chbase + n);
                    hF[(((size_t)b * COUT + chbase + n) << 12) + pix0 + p] = v;
                }
            }
            int obase = (MODE == 0) ? (asel * 320 + chbase) : chbase;
            int odim  = (MODE == 0) ? CAT2 : COUT;
            for (int idx = tid; idx < 80 * 64; idx += 256) {
                int n = idx >> 6, p2 = idx & 63;
                float v0 = fst[n * 132 + p2 * 2];
                float v1 = fst[n * 132 + p2 * 2 + 1];
                if (MODE == 0) {
                    float bv = __ldg(bias + chbase + n);
                    v0 += bv; v1 += bv;
                }
                *(uint32_t*)(O + (((size_t)b * odim + obase + n) << 12) + pix0 + p2 * 2)
                    = hpack(__float2half_rn(v0), __float2half_rn(v1));
            }
        }
        __syncthreads();
    }
}

// ---------------- launch ----------------
extern "C" void kernel_launch(void* const* d_in, const int* in_sizes, int n_in,
                              void* d_out, int out_size) {
    const float* x      = (const float*)d_in[0];
    const float* weight = (const float*)d_in[1];
    const float* bias   = (const float*)d_in[2];
    const float* w_down = (const float*)d_in[3];
    const float* w_up   = (const float*)d_in[4];
    const float* scale  = (const float*)d_in[5];
    const float* offset = (const float*)d_in[6];
    float* out = (float*)d_out;

    __half *xh, *Ac, *Ad, *wt, *wd, *wu, *ct, *dn;
    float *hF;
    cudaGetSymbolAddress((void**)&xh, g_xh);
    cudaGetSymbolAddress((void**)&Ac, g_Ac); cudaGetSymbolAddress((void**)&Ad, g_Ad);
    cudaGetSymbolAddress((void**)&wt, g_wt); cudaGetSymbolAddress((void**)&wd, g_wd);
    cudaGetSymbolAddress((void**)&wu, g_wu);
    cudaGetSymbolAddress((void**)&ct, g_ct); cudaGetSymbolAddress((void**)&dn, g_dn);
    cudaGetSymbolAddress((void**)&hF, g_hF);

    cudaFuncSetAttribute(gemm_mma<0>, cudaFuncAttributeMaxDynamicSharedMemorySize, SMEMB);
    cudaFuncSetAttribute(gemm_mma<1>, cudaFuncAttributeMaxDynamicSharedMemorySize, SMEMB);
    cudaFuncSetAttribute(gemm_mma<2>, cudaFuncAttributeMaxDynamicSharedMemorySize, SMEMB);

    // #1: unified prep
    prep_all<<<PREP_TOT / 256, 256>>>(weight, w_down, w_up, scale, x, offset,
                                      wt, wd, wu, xh);
    // #2: per-tap im2col
    im2col_k<<<dim3(40, 9, BATCH), 256>>>(xh, Ac, Ad);
    // #3: big dual GEMM
    gemm_mma<0><<<dim3(HW / 128, 4, BATCH), 256, SMEMB>>>(
        Ad, Ac, wt, CK, bias, hF, ct, nullptr);
    // #4 (profiled): down
    gemm_mma<1><<<dim3(HW / 128, 2, BATCH), 256, SMEMB>>>(
        ct, nullptr, wd, CAT2, nullptr, nullptr, dn, nullptr);
    // #5: up + residual (scale folded into wu)
    gemm_mma<2><<<dim3(HW / 128, 2, BATCH), 256, SMEMB>>>(
        dn, nullptr, wu, COUT, nullptr, hF, nullptr, out);
}